// round 10
// baseline (speedup 1.0000x reference)
#include <cuda_runtime.h>
#include <cuda_fp16.h>
#include <math.h>
#include <stdint.h>

// ---------------- problem constants ----------------
#define BB   8
#define NN   16384
#define CC   640
#define HH   256
#define OO   128
#define MTOT (BB * NN)          // 131072
#define THRESH 0.4f

// ---------------- tiling ----------------
#define MT      64              // M rows per CTA
#define NB      (HH + OO)       // 384 stacked B rows (w1 then wo)
#define NCH     (CC / 16)       // 40 k-chunks of 16
#define RSTRIDE 48              // smem row stride bytes (16 fp16 = 32B data, padded)
#define NTHR    512             // 16 warps: 2 (M) x 8 (N)

// per-stage smem: A_hi | A_lo | B_hi (no B_lo needed: 2-product scheme)
#define ST_A_HI   0
#define ST_A_LO   (MT * RSTRIDE)                 // 3072
#define ST_B_HI   (2 * MT * RSTRIDE)             // 6144
#define STAGE_SZ  (ST_B_HI + NB * RSTRIDE)       // 24576
#define NSTAGE    3
#define SM_HDR    2048                            // part[6][64] + sscore[64]
#define SMEM_TOTAL (SM_HDR + NSTAGE * STAGE_SZ)   // 75776

// weight image (hi limb only): [chunk][row 0..383][16 fp16] = 12288 B/chunk
#define WCHUNK_B  (NB * 16 * 2)

// ---------------- scratch ----------------
__device__ float g_scores[MTOT];
__device__ int   g_src[MTOT];
__device__ int   g_counts[BB];
__device__ float g_feats[(size_t)MTOT * OO];              // 64 MB
__device__ __half g_w[NCH * NB * 16];                     // 0.96 MB

// ---------------- helpers ----------------
__device__ __forceinline__ uint32_t smem_u32(const void* p) {
    uint32_t a;
    asm("{ .reg .u64 t; cvta.to.shared.u64 t, %1; cvt.u32.u64 %0, t; }" : "=r"(a) : "l"(p));
    return a;
}
__device__ __forceinline__ void ldsm_x4(uint32_t& r0, uint32_t& r1, uint32_t& r2, uint32_t& r3, uint32_t a) {
    asm volatile("ldmatrix.sync.aligned.m8n8.x4.shared.b16 {%0,%1,%2,%3}, [%4];"
                 : "=r"(r0), "=r"(r1), "=r"(r2), "=r"(r3) : "r"(a));
}
__device__ __forceinline__ void mma_f32(float* c, uint32_t a0, uint32_t a1, uint32_t a2, uint32_t a3,
                                        uint32_t b0, uint32_t b1) {
    asm volatile(
        "mma.sync.aligned.m16n8k16.row.col.f32.f16.f16.f32 "
        "{%0,%1,%2,%3}, {%4,%5,%6,%7}, {%8,%9}, {%0,%1,%2,%3};"
        : "+f"(c[0]), "+f"(c[1]), "+f"(c[2]), "+f"(c[3])
        : "r"(a0), "r"(a1), "r"(a2), "r"(a3), "r"(b0), "r"(b1));
}
__device__ __forceinline__ void cp16(uint32_t dst, const void* src) {
    asm volatile("cp.async.cg.shared.global [%0], [%1], 16;" :: "r"(dst), "l"(src));
}
#define CP_COMMIT() asm volatile("cp.async.commit_group;" ::: "memory")
#define CP_WAIT(n)  asm volatile("cp.async.wait_group %0;" :: "n"(n) : "memory")

__device__ __forceinline__ uint32_t pack_h2(float x, float y) {
    __half2 h = __floats2half2_rn(x, y);
    return *(uint32_t*)&h;
}

// =====================================================================
// Prologue: weights fp32 -> hi fp16 packed image (hi limb only)
// =====================================================================
__global__ __launch_bounds__(256) void k_wconv(const float* __restrict__ w1,
                                               const float* __restrict__ wo)
{
    int g = blockIdx.x * 256 + threadIdx.x;
    if (g >= NCH * NB * 16) return;
    int c   = g / (NB * 16);
    int rem = g - c * (NB * 16);
    int r   = rem >> 4;
    int kk  = rem & 15;
    int k   = c * 16 + kk;
    float v = (r < HH) ? w1[(size_t)k * HH + r] : wo[(size_t)k * OO + (r - HH)];
    g_w[((size_t)c * NB + r) * 16 + kk] = __float2half_rn(v);
}

// =====================================================================
// Main fused kernel (fp16 split-A x fp16 B, 2 products, all f32-acc)
// =====================================================================
__device__ __forceinline__ void copyB_async(uint32_t sb, int st, int ch, int tid) {
    const char* src = (const char*)g_w + (size_t)ch * WCHUNK_B;
    uint32_t dstb = sb + SM_HDR + st * STAGE_SZ + ST_B_HI;
#pragma unroll
    for (int i = 0; i < 2; i++) {
        int p = tid + i * NTHR;                // 16B unit index; 768 total
        if (p < 768) {
            int row = p >> 1;
            int h = p & 1;
            uint32_t dst = dstb + row * RSTRIDE + h * 16;
            cp16(dst, src + (size_t)p * 16);
        }
    }
}

// thread t: row = t>>3 (0..63), pair = t&7; store 2 fp16 hi + 2 fp16 lo
__device__ __forceinline__ void convA_st(uint32_t sb, int st, float2 v, int arow, int apr) {
    __half hx = __float2half_rn(v.x);
    __half hy = __float2half_rn(v.y);
    uint32_t h0 = pack_h2(v.x, v.y);
    float rx = v.x - __half2float(hx);
    float ry = v.y - __half2float(hy);
    uint32_t l0 = pack_h2(rx, ry);
    uint32_t base = sb + SM_HDR + st * STAGE_SZ + arow * RSTRIDE + apr * 4;
    asm volatile("st.shared.b32 [%0], %1;" :: "r"(base + ST_A_HI), "r"(h0) : "memory");
    asm volatile("st.shared.b32 [%0], %1;" :: "r"(base + ST_A_LO), "r"(l0) : "memory");
}

__global__ __launch_bounds__(NTHR, 1) void k_main(
    const float* __restrict__ X,
    const float* __restrict__ b1, const float* __restrict__ w2,
    const float* __restrict__ b2, const float* __restrict__ bo)
{
    extern __shared__ char smem[];
    const uint32_t sb = smem_u32(smem);
    const int tid = threadIdx.x;
    const int wid = tid >> 5;
    const int lane = tid & 31;
    const int nw = wid & 7;            // N warp group: 48 cols each
    const int mw = wid >> 3;           // M warp group: 32 rows each
    const int q = lane & 3;
    const int r = lane >> 2;
    const int m0 = blockIdx.x * MT;
    const int n0 = nw * 48;

    float* part   = (float*)smem;          // [6][64]
    float* sscore = (float*)smem + 384;    // [64]

    const int arow = tid >> 3;
    const int apr = tid & 7;
    const float* aptr = X + (size_t)(m0 + arow) * CC + apr * 2;

    // ---- prologue ----
    float2 areg = *(const float2*)(aptr);               // chunk 0
    copyB_async(sb, 0, 0, tid); CP_COMMIT();
    convA_st(sb, 0, areg, arow, apr);
    areg = *(const float2*)(aptr + 16);                 // chunk 1
    copyB_async(sb, 1, 1, tid); CP_COMMIT();
    CP_WAIT(1);
    __syncthreads();

    float c[48];
#pragma unroll
    for (int i = 0; i < 48; i++) c[i] = 0.f;

    const uint32_t aoff0 = (uint32_t)((mw * 32 + (lane & 15)) * RSTRIDE + ((lane >> 4) << 4));
    const uint32_t aoff1 = aoff0 + 16 * RSTRIDE;
    const uint32_t boff = (uint32_t)(((lane & 7) + ((lane >> 4) << 3)) * RSTRIDE + (((lane >> 3) & 1) << 4));

    for (int ch = 0; ch < NCH; ch++) {
        const uint32_t stb = sb + SM_HDR + (ch % NSTAGE) * STAGE_SZ;
        uint32_t ah[2][4], al[2][4];
        ldsm_x4(ah[0][0], ah[0][1], ah[0][2], ah[0][3], stb + ST_A_HI + aoff0);
        ldsm_x4(ah[1][0], ah[1][1], ah[1][2], ah[1][3], stb + ST_A_HI + aoff1);
        ldsm_x4(al[0][0], al[0][1], al[0][2], al[0][3], stb + ST_A_LO + aoff0);
        ldsm_x4(al[1][0], al[1][1], al[1][2], al[1][3], stb + ST_A_LO + aoff1);
        const uint32_t bb = stb + ST_B_HI + (uint32_t)(n0 * RSTRIDE) + boff;
#pragma unroll
        for (int jp = 0; jp < 3; jp++) {
            uint32_t bh[4];
            ldsm_x4(bh[0], bh[1], bh[2], bh[3], bb + jp * 16 * RSTRIDE);
#pragma unroll
            for (int t = 0; t < 2; t++) {
#pragma unroll
                for (int s = 0; s < 2; s++) {
                    float* cj = c + (t * 6 + jp * 2 + s) * 4;
                    mma_f32(cj, ah[t][0], ah[t][1], ah[t][2], ah[t][3], bh[2*s], bh[2*s+1]); // hi*hi
                    mma_f32(cj, al[t][0], al[t][1], al[t][2], al[t][3], bh[2*s], bh[2*s+1]); // lo*hi
                }
            }
        }

        if (ch + 1 < NCH) {
            convA_st(sb, (ch + 1) % NSTAGE, areg, arow, apr);
            if (ch + 2 < NCH) {
                areg = *(const float2*)(aptr + (size_t)(ch + 2) * 16);
                copyB_async(sb, (ch + 2) % NSTAGE, ch + 2, tid); CP_COMMIT();
                CP_WAIT(1);
            } else {
                CP_WAIT(0);
            }
            __syncthreads();
        }
    }

    // ---- deterministic score reduction ----
    __syncthreads();
    if (tid < 64) {
#pragma unroll
        for (int kk = 0; kk < 6; kk++) part[kk * 64 + tid] = 0.f;
    }
    __syncthreads();

    if (nw < 6) {
        const int jmax = (nw == 5) ? 2 : 6;
#pragma unroll
        for (int t = 0; t < 2; t++) {
            float pr = 0.f, pr8 = 0.f;
#pragma unroll
            for (int j = 0; j < 6; j++) {
                if (j >= jmax) break;
                int col = n0 + j * 8 + 2 * q;
                float w2a = w2[col], w2b = w2[col + 1];
                float b1a = b1[col], b1b = b1[col + 1];
                const float* cj = c + (t * 6 + j) * 4;
                pr  = fmaf(fmaxf(cj[0] + b1a, 0.f), w2a, pr);
                pr  = fmaf(fmaxf(cj[1] + b1b, 0.f), w2b, pr);
                pr8 = fmaf(fmaxf(cj[2] + b1a, 0.f), w2a, pr8);
                pr8 = fmaf(fmaxf(cj[3] + b1b, 0.f), w2b, pr8);
            }
            pr  += __shfl_xor_sync(0xFFFFFFFFu, pr, 1);
            pr  += __shfl_xor_sync(0xFFFFFFFFu, pr, 2);
            pr8 += __shfl_xor_sync(0xFFFFFFFFu, pr8, 1);
            pr8 += __shfl_xor_sync(0xFFFFFFFFu, pr8, 2);
            if (q == 0) {
                int row = mw * 32 + t * 16 + r;
                part[nw * 64 + row]     = pr;
                part[nw * 64 + row + 8] = pr8;
            }
        }
    }
    __syncthreads();

    if (tid < 64) {
        float logit = b2[0];
#pragma unroll
        for (int kk = 0; kk < 6; kk++) logit += part[kk * 64 + tid];
        float s = 1.f / (1.f + expf(-logit));
        g_scores[m0 + tid] = s;
        sscore[tid] = s;
    }
    __syncthreads();

    // ---- feats: cols 256..383 live in nw 5 (j>=2), 6, 7 ----
    if (nw >= 5) {
        const int jstart = (nw == 5) ? 2 : 0;
#pragma unroll
        for (int t = 0; t < 2; t++) {
#pragma unroll
            for (int j = 0; j < 6; j++) {
                if (j < jstart) continue;
                int fcol = n0 + j * 8 - 256 + 2 * q;
                int row = mw * 32 + t * 16 + r;
                float s1 = sscore[row], s2 = sscore[row + 8];
                float boa = bo[fcol], bob = bo[fcol + 1];
                const float* cj = c + (t * 6 + j) * 4;
                float2 v1 = make_float2(fmaf(s1, cj[0], boa), fmaf(s1, cj[1], bob));
                float2 v2 = make_float2(fmaf(s2, cj[2], boa), fmaf(s2, cj[3], bob));
                *(float2*)(g_feats + (size_t)(m0 + row) * OO + fcol) = v1;
                *(float2*)(g_feats + (size_t)(m0 + row + 8) * OO + fcol) = v2;
            }
        }
    }
}

// =====================================================================
// Per-batch stream-compaction scan (1 CTA per batch)
// =====================================================================
__global__ __launch_bounds__(256) void k_scan()
{
    const int b = blockIdx.x;
    const int base = b << 14;
    const int t = threadIdx.x;
    const int chunk = t * 64;

    int c = 0;
    for (int e = 0; e < 64; e++)
        c += (g_scores[base + chunk + e] > THRESH) ? 1 : 0;

    const int lane = t & 31, wid = t >> 5;
    int v = c;
#pragma unroll
    for (int o = 1; o < 32; o <<= 1) {
        int u = __shfl_up_sync(0xFFFFFFFFu, v, o);
        if (lane >= o) v += u;
    }
    __shared__ int wsum[8];
    if (lane == 31) wsum[wid] = v;
    __syncthreads();
    int woff = 0;
    for (int w = 0; w < wid; w++) woff += wsum[w];
    int p = woff + v - c;

    for (int e = 0; e < 64; e++) {
        int n = chunk + e;
        if (g_scores[base + n] > THRESH) {
            g_src[base + p] = n;
            p++;
        }
    }
    if (t == 255) g_counts[b] = p;
}

// =====================================================================
// Finalize: warp-per-row gather g_feats[src] -> kp_out[slot], coords, mask
// =====================================================================
__global__ __launch_bounds__(256) void k_final(
    const float* __restrict__ coords, float* __restrict__ kp,
    float* __restrict__ co, float* __restrict__ mk)
{
    const int w = blockIdx.x * 8 + (threadIdx.x >> 5);
    const int lane = threadIdx.x & 31;
    const int b = w >> 14;
    const int j = w & (NN - 1);
    const int cnt = g_counts[b];
    float4* dst = (float4*)(kp + (size_t)w * OO);
    if (j < cnt) {
        const int srow = (b << 14) + g_src[w];
        const float4* src = (const float4*)(g_feats + (size_t)srow * OO);
        dst[lane] = src[lane];
        if (lane == 0) {
            float c0 = coords[(size_t)srow * 3 + 0];
            float c1 = coords[(size_t)srow * 3 + 1];
            float c2 = coords[(size_t)srow * 3 + 2];
            co[(size_t)w * 3 + 0] = c0;
            co[(size_t)w * 3 + 1] = c1;
            co[(size_t)w * 3 + 2] = c2;
            mk[w] = ((c0 == 0.f) || (c1 == 0.f) || (c2 == 0.f)) ? 1.f : 0.f;
        }
    } else {
        dst[lane] = make_float4(0.f, 0.f, 0.f, 0.f);
        if (lane == 0) {
            co[(size_t)w * 3 + 0] = 0.f;
            co[(size_t)w * 3 + 1] = 0.f;
            co[(size_t)w * 3 + 2] = 0.f;
            mk[w] = 1.f;
        }
    }
}

// =====================================================================
extern "C" void kernel_launch(void* const* d_in, const int* in_sizes, int n_in,
                              void* d_out, int out_size)
{
    const float* X  = (const float*)d_in[0];
    const float* PC = (const float*)d_in[1];
    const float* w1 = (const float*)d_in[2];
    const float* b1 = (const float*)d_in[3];
    const float* w2 = (const float*)d_in[4];
    const float* b2 = (const float*)d_in[5];
    const float* wo = (const float*)d_in[6];
    const float* bo = (const float*)d_in[7];

    float* out    = (float*)d_out;
    float* kp_out = out;                                   // [B,N,O]
    float* co_out = out + (size_t)MTOT * OO;               // [B,N,3]
    float* mk_out = co_out + (size_t)MTOT * 3;             // [B,N]

    static int smem_set = 0;
    if (!smem_set) {
        cudaFuncSetAttribute(k_main, cudaFuncAttributeMaxDynamicSharedMemorySize, SMEM_TOTAL);
        smem_set = 1;
    }

    k_wconv<<<(NCH * NB * 16 + 255) / 256, 256>>>(w1, wo);
    k_main<<<MTOT / MT, NTHR, SMEM_TOTAL>>>(X, b1, w2, b2, bo);
    k_scan<<<BB, 256>>>();
    k_final<<<MTOT / 8, 256>>>(PC, kp_out, co_out, mk_out);
}

// round 11
// speedup vs baseline: 1.0023x; 1.0023x over previous
#include <cuda_runtime.h>
#include <cuda_fp16.h>
#include <math.h>
#include <stdint.h>

// ---------------- problem constants ----------------
#define BB   8
#define NN   16384
#define CC   640
#define HH   256
#define OO   128
#define MTOT (BB * NN)          // 131072
#define THRESH 0.4f

// ---------------- tiling ----------------
#define MT      64              // M rows per CTA
#define NB      (HH + OO)       // 384 stacked B rows (w1 then wo)
#define NCH     (CC / 16)       // 40 k-chunks of 16
#define RSTRIDE 48              // smem row stride bytes (16 fp16 = 32B data, padded)
#define NTHR    512             // 16 warps: 2 (M) x 8 (N)

// per-stage smem: A_hi | A_lo | B_hi (no B_lo needed: 2-product scheme)
#define ST_A_HI   0
#define ST_A_LO   (MT * RSTRIDE)                 // 3072
#define ST_B_HI   (2 * MT * RSTRIDE)             // 6144
#define STAGE_SZ  (ST_B_HI + NB * RSTRIDE)       // 24576
#define NSTAGE    3
#define SM_HDR    2048                            // part[6][64] + sscore[64]
#define SMEM_TOTAL (SM_HDR + NSTAGE * STAGE_SZ)   // 75776

// weight image (hi limb only): [chunk][row 0..383][16 fp16] = 12288 B/chunk
#define WCHUNK_B  (NB * 16 * 2)

// ---------------- scratch ----------------
__device__ float g_scores[MTOT];
__device__ int   g_src[MTOT];
__device__ int   g_counts[BB];
__device__ float g_feats[(size_t)MTOT * OO];              // 64 MB
__device__ __half g_w[NCH * NB * 16];                     // 0.96 MB

// ---------------- helpers ----------------
__device__ __forceinline__ uint32_t smem_u32(const void* p) {
    uint32_t a;
    asm("{ .reg .u64 t; cvta.to.shared.u64 t, %1; cvt.u32.u64 %0, t; }" : "=r"(a) : "l"(p));
    return a;
}
__device__ __forceinline__ void ldsm_x4(uint32_t& r0, uint32_t& r1, uint32_t& r2, uint32_t& r3, uint32_t a) {
    asm volatile("ldmatrix.sync.aligned.m8n8.x4.shared.b16 {%0,%1,%2,%3}, [%4];"
                 : "=r"(r0), "=r"(r1), "=r"(r2), "=r"(r3) : "r"(a));
}
__device__ __forceinline__ void mma_f32(float* c, uint32_t a0, uint32_t a1, uint32_t a2, uint32_t a3,
                                        uint32_t b0, uint32_t b1) {
    asm volatile(
        "mma.sync.aligned.m16n8k16.row.col.f32.f16.f16.f32 "
        "{%0,%1,%2,%3}, {%4,%5,%6,%7}, {%8,%9}, {%0,%1,%2,%3};"
        : "+f"(c[0]), "+f"(c[1]), "+f"(c[2]), "+f"(c[3])
        : "r"(a0), "r"(a1), "r"(a2), "r"(a3), "r"(b0), "r"(b1));
}
__device__ __forceinline__ void cp16(uint32_t dst, const void* src) {
    asm volatile("cp.async.cg.shared.global [%0], [%1], 16;" :: "r"(dst), "l"(src));
}
#define CP_COMMIT() asm volatile("cp.async.commit_group;" ::: "memory")
#define CP_WAIT(n)  asm volatile("cp.async.wait_group %0;" :: "n"(n) : "memory")

__device__ __forceinline__ uint32_t pack_h2(float x, float y) {
    __half2 h = __floats2half2_rn(x, y);
    return *(uint32_t*)&h;
}

// =====================================================================
// Prologue: weights fp32 -> hi fp16 packed image (hi limb only)
// =====================================================================
__global__ __launch_bounds__(256) void k_wconv(const float* __restrict__ w1,
                                               const float* __restrict__ wo)
{
    int g = blockIdx.x * 256 + threadIdx.x;
    if (g >= NCH * NB * 16) return;
    int c   = g / (NB * 16);
    int rem = g - c * (NB * 16);
    int r   = rem >> 4;
    int kk  = rem & 15;
    int k   = c * 16 + kk;
    float v = (r < HH) ? w1[(size_t)k * HH + r] : wo[(size_t)k * OO + (r - HH)];
    g_w[((size_t)c * NB + r) * 16 + kk] = __float2half_rn(v);
}

// =====================================================================
// Main fused kernel (fp16 split-A x fp16 B, 2 products, all f32-acc)
// =====================================================================
__device__ __forceinline__ void copyB_async(uint32_t sb, int st, int ch, int tid) {
    const char* src = (const char*)g_w + (size_t)ch * WCHUNK_B;
    uint32_t dstb = sb + SM_HDR + st * STAGE_SZ + ST_B_HI;
#pragma unroll
    for (int i = 0; i < 2; i++) {
        int p = tid + i * NTHR;                // 16B unit index; 768 total
        if (p < 768) {
            int row = p >> 1;
            int h = p & 1;
            uint32_t dst = dstb + row * RSTRIDE + h * 16;
            cp16(dst, src + (size_t)p * 16);
        }
    }
}

// thread t: row = t>>3 (0..63), pair = t&7; store 2 fp16 hi + 2 fp16 lo
__device__ __forceinline__ void convA_st(uint32_t sb, int st, float2 v, int arow, int apr) {
    __half hx = __float2half_rn(v.x);
    __half hy = __float2half_rn(v.y);
    uint32_t h0 = pack_h2(v.x, v.y);
    float rx = v.x - __half2float(hx);
    float ry = v.y - __half2float(hy);
    uint32_t l0 = pack_h2(rx, ry);
    uint32_t base = sb + SM_HDR + st * STAGE_SZ + arow * RSTRIDE + apr * 4;
    asm volatile("st.shared.b32 [%0], %1;" :: "r"(base + ST_A_HI), "r"(h0) : "memory");
    asm volatile("st.shared.b32 [%0], %1;" :: "r"(base + ST_A_LO), "r"(l0) : "memory");
}

__global__ __launch_bounds__(NTHR, 1) void k_main(
    const float* __restrict__ X,
    const float* __restrict__ b1, const float* __restrict__ w2,
    const float* __restrict__ b2, const float* __restrict__ bo)
{
    extern __shared__ char smem[];
    const uint32_t sb = smem_u32(smem);
    const int tid = threadIdx.x;
    const int wid = tid >> 5;
    const int lane = tid & 31;
    const int nw = wid & 7;            // N warp group: 48 cols each
    const int mw = wid >> 3;           // M warp group: 32 rows each
    const int q = lane & 3;
    const int r = lane >> 2;
    const int m0 = blockIdx.x * MT;
    const int n0 = nw * 48;

    float* part   = (float*)smem;          // [6][64]
    float* sscore = (float*)smem + 384;    // [64]

    const int arow = tid >> 3;
    const int apr = tid & 7;
    const float* aptr = X + (size_t)(m0 + arow) * CC + apr * 2;

    // ---- prologue ----
    float2 areg = *(const float2*)(aptr);               // chunk 0
    copyB_async(sb, 0, 0, tid); CP_COMMIT();
    convA_st(sb, 0, areg, arow, apr);
    areg = *(const float2*)(aptr + 16);                 // chunk 1
    copyB_async(sb, 1, 1, tid); CP_COMMIT();
    CP_WAIT(1);
    __syncthreads();

    float c[48];
#pragma unroll
    for (int i = 0; i < 48; i++) c[i] = 0.f;

    const uint32_t aoff0 = (uint32_t)((mw * 32 + (lane & 15)) * RSTRIDE + ((lane >> 4) << 4));
    const uint32_t aoff1 = aoff0 + 16 * RSTRIDE;
    const uint32_t boff = (uint32_t)(((lane & 7) + ((lane >> 4) << 3)) * RSTRIDE + (((lane >> 3) & 1) << 4));

    for (int ch = 0; ch < NCH; ch++) {
        const uint32_t stb = sb + SM_HDR + (ch % NSTAGE) * STAGE_SZ;
        uint32_t ah[2][4], al[2][4];
        ldsm_x4(ah[0][0], ah[0][1], ah[0][2], ah[0][3], stb + ST_A_HI + aoff0);
        ldsm_x4(ah[1][0], ah[1][1], ah[1][2], ah[1][3], stb + ST_A_HI + aoff1);
        ldsm_x4(al[0][0], al[0][1], al[0][2], al[0][3], stb + ST_A_LO + aoff0);
        ldsm_x4(al[1][0], al[1][1], al[1][2], al[1][3], stb + ST_A_LO + aoff1);
        const uint32_t bb = stb + ST_B_HI + (uint32_t)(n0 * RSTRIDE) + boff;
#pragma unroll
        for (int jp = 0; jp < 3; jp++) {
            uint32_t bh[4];
            ldsm_x4(bh[0], bh[1], bh[2], bh[3], bb + jp * 16 * RSTRIDE);
#pragma unroll
            for (int t = 0; t < 2; t++) {
#pragma unroll
                for (int s = 0; s < 2; s++) {
                    float* cj = c + (t * 6 + jp * 2 + s) * 4;
                    mma_f32(cj, ah[t][0], ah[t][1], ah[t][2], ah[t][3], bh[2*s], bh[2*s+1]); // hi*hi
                    mma_f32(cj, al[t][0], al[t][1], al[t][2], al[t][3], bh[2*s], bh[2*s+1]); // lo*hi
                }
            }
        }

        if (ch + 1 < NCH) {
            convA_st(sb, (ch + 1) % NSTAGE, areg, arow, apr);
            if (ch + 2 < NCH) {
                areg = *(const float2*)(aptr + (size_t)(ch + 2) * 16);
                copyB_async(sb, (ch + 2) % NSTAGE, ch + 2, tid); CP_COMMIT();
                CP_WAIT(1);
            } else {
                CP_WAIT(0);
            }
            __syncthreads();
        }
    }

    // ---- deterministic score reduction ----
    __syncthreads();
    if (tid < 64) {
#pragma unroll
        for (int kk = 0; kk < 6; kk++) part[kk * 64 + tid] = 0.f;
    }
    __syncthreads();

    if (nw < 6) {
        const int jmax = (nw == 5) ? 2 : 6;
#pragma unroll
        for (int t = 0; t < 2; t++) {
            float pr = 0.f, pr8 = 0.f;
#pragma unroll
            for (int j = 0; j < 6; j++) {
                if (j >= jmax) break;
                int col = n0 + j * 8 + 2 * q;
                float w2a = w2[col], w2b = w2[col + 1];
                float b1a = b1[col], b1b = b1[col + 1];
                const float* cj = c + (t * 6 + j) * 4;
                pr  = fmaf(fmaxf(cj[0] + b1a, 0.f), w2a, pr);
                pr  = fmaf(fmaxf(cj[1] + b1b, 0.f), w2b, pr);
                pr8 = fmaf(fmaxf(cj[2] + b1a, 0.f), w2a, pr8);
                pr8 = fmaf(fmaxf(cj[3] + b1b, 0.f), w2b, pr8);
            }
            pr  += __shfl_xor_sync(0xFFFFFFFFu, pr, 1);
            pr  += __shfl_xor_sync(0xFFFFFFFFu, pr, 2);
            pr8 += __shfl_xor_sync(0xFFFFFFFFu, pr8, 1);
            pr8 += __shfl_xor_sync(0xFFFFFFFFu, pr8, 2);
            if (q == 0) {
                int row = mw * 32 + t * 16 + r;
                part[nw * 64 + row]     = pr;
                part[nw * 64 + row + 8] = pr8;
            }
        }
    }
    __syncthreads();

    if (tid < 64) {
        float logit = b2[0];
#pragma unroll
        for (int kk = 0; kk < 6; kk++) logit += part[kk * 64 + tid];
        float s = 1.f / (1.f + expf(-logit));
        g_scores[m0 + tid] = s;
        sscore[tid] = s;
    }
    __syncthreads();

    // ---- feats: cols 256..383 live in nw 5 (j>=2), 6, 7 ----
    if (nw >= 5) {
        const int jstart = (nw == 5) ? 2 : 0;
#pragma unroll
        for (int t = 0; t < 2; t++) {
#pragma unroll
            for (int j = 0; j < 6; j++) {
                if (j < jstart) continue;
                int fcol = n0 + j * 8 - 256 + 2 * q;
                int row = mw * 32 + t * 16 + r;
                float s1 = sscore[row], s2 = sscore[row + 8];
                float boa = bo[fcol], bob = bo[fcol + 1];
                const float* cj = c + (t * 6 + j) * 4;
                float2 v1 = make_float2(fmaf(s1, cj[0], boa), fmaf(s1, cj[1], bob));
                float2 v2 = make_float2(fmaf(s2, cj[2], boa), fmaf(s2, cj[3], bob));
                *(float2*)(g_feats + (size_t)(m0 + row) * OO + fcol) = v1;
                *(float2*)(g_feats + (size_t)(m0 + row + 8) * OO + fcol) = v2;
            }
        }
    }
}

// =====================================================================
// Per-batch stream-compaction scan (1 CTA per batch)
// =====================================================================
__global__ __launch_bounds__(256) void k_scan()
{
    const int b = blockIdx.x;
    const int base = b << 14;
    const int t = threadIdx.x;
    const int chunk = t * 64;

    int c = 0;
    for (int e = 0; e < 64; e++)
        c += (g_scores[base + chunk + e] > THRESH) ? 1 : 0;

    const int lane = t & 31, wid = t >> 5;
    int v = c;
#pragma unroll
    for (int o = 1; o < 32; o <<= 1) {
        int u = __shfl_up_sync(0xFFFFFFFFu, v, o);
        if (lane >= o) v += u;
    }
    __shared__ int wsum[8];
    if (lane == 31) wsum[wid] = v;
    __syncthreads();
    int woff = 0;
    for (int w = 0; w < wid; w++) woff += wsum[w];
    int p = woff + v - c;

    for (int e = 0; e < 64; e++) {
        int n = chunk + e;
        if (g_scores[base + n] > THRESH) {
            g_src[base + p] = n;
            p++;
        }
    }
    if (t == 255) g_counts[b] = p;
}

// =====================================================================
// Finalize: warp-per-row gather g_feats[src] -> kp_out[slot], coords, mask
// =====================================================================
__global__ __launch_bounds__(256) void k_final(
    const float* __restrict__ coords, float* __restrict__ kp,
    float* __restrict__ co, float* __restrict__ mk)
{
    const int w = blockIdx.x * 8 + (threadIdx.x >> 5);
    const int lane = threadIdx.x & 31;
    const int b = w >> 14;
    const int j = w & (NN - 1);
    const int cnt = g_counts[b];
    float4* dst = (float4*)(kp + (size_t)w * OO);
    if (j < cnt) {
        const int srow = (b << 14) + g_src[w];
        const float4* src = (const float4*)(g_feats + (size_t)srow * OO);
        dst[lane] = src[lane];
        if (lane == 0) {
            float c0 = coords[(size_t)srow * 3 + 0];
            float c1 = coords[(size_t)srow * 3 + 1];
            float c2 = coords[(size_t)srow * 3 + 2];
            co[(size_t)w * 3 + 0] = c0;
            co[(size_t)w * 3 + 1] = c1;
            co[(size_t)w * 3 + 2] = c2;
            mk[w] = ((c0 == 0.f) || (c1 == 0.f) || (c2 == 0.f)) ? 1.f : 0.f;
        }
    } else {
        dst[lane] = make_float4(0.f, 0.f, 0.f, 0.f);
        if (lane == 0) {
            co[(size_t)w * 3 + 0] = 0.f;
            co[(size_t)w * 3 + 1] = 0.f;
            co[(size_t)w * 3 + 2] = 0.f;
            mk[w] = 1.f;
        }
    }
}

// =====================================================================
extern "C" void kernel_launch(void* const* d_in, const int* in_sizes, int n_in,
                              void* d_out, int out_size)
{
    const float* X  = (const float*)d_in[0];
    const float* PC = (const float*)d_in[1];
    const float* w1 = (const float*)d_in[2];
    const float* b1 = (const float*)d_in[3];
    const float* w2 = (const float*)d_in[4];
    const float* b2 = (const float*)d_in[5];
    const float* wo = (const float*)d_in[6];
    const float* bo = (const float*)d_in[7];

    float* out    = (float*)d_out;
    float* kp_out = out;                                   // [B,N,O]
    float* co_out = out + (size_t)MTOT * OO;               // [B,N,3]
    float* mk_out = co_out + (size_t)MTOT * 3;             // [B,N]

    static int smem_set = 0;
    if (!smem_set) {
        cudaFuncSetAttribute(k_main, cudaFuncAttributeMaxDynamicSharedMemorySize, SMEM_TOTAL);
        smem_set = 1;
    }

    k_wconv<<<(NCH * NB * 16 + 255) / 256, 256>>>(w1, wo);
    k_main<<<MTOT / MT, NTHR, SMEM_TOTAL>>>(X, b1, w2, b2, bo);
    k_scan<<<BB, 256>>>();
    k_final<<<MTOT / 8, 256>>>(PC, kp_out, co_out, mk_out);
}